// round 8
// baseline (speedup 1.0000x reference)
#include <cuda_runtime.h>
#include <cuda_bf16.h>
#include <stdint.h>

#define PP 20
#define VPW 2          // voxels per warp
#define WARPS 2
#define THREADS 64
#define ROWS 48        // 3 m16 tiles: v0 p0-15, v1 p0-15, leftovers(8)+zeros(8)
#define ASTR 80        // bytes per A row

// precomputed by lef_prep: B fragments (BN-scale folded, permuted, bf16 hi/lo)
// layout: [h(2)][lane(32)][ 16 x hi | 16 x lo ]
__device__ uint32_t g_Btab[2 * 32 * 32];
__device__ float    g_shift[64];

__device__ __forceinline__ uint32_t smem_u32(const void* p) {
    uint32_t a;
    asm("{ .reg .u64 t; cvta.to.shared.u64 t, %1; cvt.u32.u64 %0, t; }" : "=r"(a) : "l"(p));
    return a;
}
__device__ __forceinline__ float sqrt_apx(float x) {
    float r; asm("sqrt.approx.f32 %0,%1;" : "=f"(r) : "f"(x)); return r;
}
__device__ __forceinline__ uint32_t pack_bf2(float x, float y) {
    __nv_bfloat162 t = __floats2bfloat162_rn(x, y);
    return *(uint32_t*)&t;
}
__device__ __forceinline__ uint32_t pack_res2(float x, float y, uint32_t hipack) {
    __nv_bfloat162 h = *(__nv_bfloat162*)&hipack;
    return pack_bf2(x - __bfloat162float(h.x), y - __bfloat162float(h.y));
}
__device__ __forceinline__ void ldmat4(uint32_t* r, uint32_t addr) {
    asm volatile("ldmatrix.sync.aligned.m8n8.x4.shared.b16 {%0,%1,%2,%3}, [%4];"
        : "=r"(r[0]), "=r"(r[1]), "=r"(r[2]), "=r"(r[3]) : "r"(addr));
}
__device__ __forceinline__ void mma16816(float* c, const uint32_t* a, const uint32_t* b) {
    asm volatile("mma.sync.aligned.m16n8k16.row.col.f32.bf16.bf16.f32 "
        "{%0,%1,%2,%3},{%4,%5,%6,%7},{%8,%9},{%0,%1,%2,%3};"
        : "+f"(c[0]), "+f"(c[1]), "+f"(c[2]), "+f"(c[3])
        : "r"(a[0]), "r"(a[1]), "r"(a[2]), "r"(a[3]), "r"(b[0]), "r"(b[1]));
}
__device__ __forceinline__ float wval(const float* __restrict__ W, int k, int n) {
    if (k < 20) return W[(7 + k) * 64 + n];
    if (k < 27) return W[(k - 20) * 64 + n];
    return 0.0f;
}

// ---- pre-kernel: build B fragment table + shift table (once) ----
__global__ void lef_prep(const float* __restrict__ W, const float* __restrict__ gamma_,
                         const float* __restrict__ beta_, const float* __restrict__ rmean,
                         const float* __restrict__ rvar)
{
    const int t = threadIdx.x;                    // 64 threads
    {
        const float s = gamma_[t] * rsqrtf(rvar[t] + 1e-3f);
        g_shift[t] = beta_[t] - rmean[t] * s;
    }
    const int h = t >> 5, lane = t & 31, t4 = lane & 3, gg = lane >> 2;
    uint32_t vals[32];
    #pragma unroll
    for (int nt = 0; nt < 4; ++nt) {
        const int nn = h * 32 + nt * 8 + gg;
        const float s = gamma_[nn] * rsqrtf(rvar[nn] + 1e-3f);
        #pragma unroll
        for (int ks = 0; ks < 2; ++ks) {
            const int k0 = ks * 16 + 2 * t4;
            const float w00 = wval(W, k0,     nn) * s;
            const float w01 = wval(W, k0 + 1, nn) * s;
            const float w10 = wval(W, k0 + 8, nn) * s;
            const float w11 = wval(W, k0 + 9, nn) * s;
            const uint32_t h0 = pack_bf2(w00, w01);
            const uint32_t h1 = pack_bf2(w10, w11);
            vals[(nt * 2 + ks) * 2 + 0] = h0;
            vals[(nt * 2 + ks) * 2 + 1] = h1;
            vals[16 + (nt * 2 + ks) * 2 + 0] = pack_res2(w00, w01, h0);
            vals[16 + (nt * 2 + ks) * 2 + 1] = pack_res2(w10, w11, h1);
        }
    }
    uint32_t* dst = &g_Btab[(h * 32 + lane) * 32];
    #pragma unroll
    for (int i = 0; i < 32; ++i) dst[i] = vals[i];
}

__global__ void __launch_bounds__(THREADS, 10) lef_mma4_kernel(
    const float4* __restrict__ feats4,
    const int*    __restrict__ num_points,
    float* __restrict__ out,
    int V)
{
    __shared__ __align__(16) uint8_t Ahi[WARPS][ROWS * ASTR];
    __shared__ __align__(16) uint8_t Alo[WARPS][ROWS * ASTR];
    __shared__ float4 cs4s[WARPS * VPW][PP];
    __shared__ float  sqs [WARPS * VPW][PP];
    __shared__ float  meanv[WARPS * VPW][3];
    __shared__ int    npvs[WARPS * VPW];
    __shared__ __align__(8) float shfs[64];

    const int tid  = threadIdx.x;
    const int warp = tid >> 5;
    const int lane = tid & 31;
    const int t4 = lane & 3, g = lane >> 2;

    if (tid < 64) shfs[tid] = g_shift[tid];

    // ---- stage features (coalesced LDG.128) ----
    const int v0 = (blockIdx.x * WARPS + warp) * VPW;
    for (int t = lane; t < VPW * PP; t += 32) {
        const int vi = t / PP, p = t - vi * PP;
        const int vv = v0 + vi;
        float4 f = make_float4(0.f, 0.f, 0.f, 0.f);
        if (vv < V) f = feats4[(size_t)v0 * PP + t];
        const int sv = warp * VPW + vi;
        cs4s[sv][p] = f;
        sqs[sv][p]  = f.x * f.x + f.y * f.y + f.z * f.z;
    }
    if (lane < VPW) {
        const int vv = v0 + lane;
        npvs[warp * VPW + lane] = (vv < V) ? num_points[vv] : 1;
    }
    __syncwarp();

    // ---- per-voxel means (unmasked sum / npts, as reference) ----
    if (lane < VPW * 3) {
        const int vi = lane / 3, d = lane - vi * 3;
        const int sv = warp * VPW + vi;
        const float* c = (const float*)&cs4s[sv][0];
        float s = 0.0f;
        #pragma unroll
        for (int p = 0; p < PP; ++p) s += c[p * 4 + d];
        meanv[sv][d] = s / (float)npvs[sv];
    }
    __syncwarp();

    // ---- assemble A rows (hi/lo bf16) ----
    // r<32: voxel r>>4, p=r&15 ; r in [32,40): voxel (r-32)>>2, p=16+((r-32)&3)
    // r in [40,48): zero rows
    const uint32_t aHiB = smem_u32(&Ahi[warp][0]);
    const uint32_t aLoB = smem_u32(&Alo[warp][0]);
    #pragma unroll
    for (int r = lane; r < ROWS; r += 32) {
        uint8_t* rowHi = &Ahi[warp][r * ASTR];
        uint8_t* rowLo = &Alo[warp][r * ASTR];
        if (r >= 40) {                         // padding rows: zero
            const uint4 z = make_uint4(0, 0, 0, 0);
            #pragma unroll
            for (int j = 0; j < 4; ++j) {
                *(uint4*)(rowHi + j * 16) = z;
                *(uint4*)(rowLo + j * 16) = z;
            }
            continue;
        }
        int vi, p;
        if (r < 32) { vi = r >> 4; p = r & 15; }
        else        { vi = (r - 32) >> 2; p = 16 + ((r - 32) & 3); }
        const int sv = warp * VPW + vi;
        const float4 a  = cs4s[sv][p];
        const float sqp = sqs[sv][p];
        const int   np  = npvs[sv];
        const float pm  = (p < np) ? 1.0f : 0.0f;
        const float m0 = meanv[sv][0], m1 = meanv[sv][1], m2 = meanv[sv][2];

        uint32_t hi[16], lo[16];
        #pragma unroll
        for (int jj = 0; jj < 10; ++jj) {
            const int q0 = 2 * jj, q1 = q0 + 1;
            const float4 b0 = cs4s[sv][q0], b1 = cs4s[sv][q1];
            float dot0 = a.x * b0.x; dot0 = fmaf(a.y, b0.y, dot0); dot0 = fmaf(a.z, b0.z, dot0);
            float dot1 = a.x * b1.x; dot1 = fmaf(a.y, b1.y, dot1); dot1 = fmaf(a.z, b1.z, dot1);
            const float d20 = (sqp + sqs[sv][q0]) - 2.0f * dot0;
            const float d21 = (sqp + sqs[sv][q1]) - 2.0f * dot1;
            const float e0 = (d20 > 0.0f && q0 < np) ? sqrt_apx(d20) : 0.0f;
            const float e1 = (d21 > 0.0f && q1 < np) ? sqrt_apx(d21) : 0.0f;
            hi[jj] = pack_bf2(e0, e1);
            lo[jj] = pack_res2(e0, e1, hi[jj]);
        }
        const float n0 = a.x * pm, n1 = a.y * pm, n2 = a.z * pm, n3 = a.w * pm;
        const float n4 = (a.x - m0) * pm, n5 = (a.y - m1) * pm, n6 = (a.z - m2) * pm;
        hi[10] = pack_bf2(n0, n1); lo[10] = pack_res2(n0, n1, hi[10]);
        hi[11] = pack_bf2(n2, n3); lo[11] = pack_res2(n2, n3, hi[11]);
        hi[12] = pack_bf2(n4, n5); lo[12] = pack_res2(n4, n5, hi[12]);
        hi[13] = pack_bf2(n6, 0.f); lo[13] = pack_res2(n6, 0.f, hi[13]);
        hi[14] = hi[15] = lo[14] = lo[15] = 0u;

        const int rot = (lane >> 3) & 3;              // de-conflict STS banks
        #pragma unroll
        for (int jj = 0; jj < 4; ++jj) {
            const int j = (jj + rot) & 3;
            *(uint4*)(rowHi + j * 16) = make_uint4(hi[4*j], hi[4*j+1], hi[4*j+2], hi[4*j+3]);
            *(uint4*)(rowLo + j * 16) = make_uint4(lo[4*j], lo[4*j+1], lo[4*j+2], lo[4*j+3]);
        }
    }
    __syncthreads();   // A tiles + shfs visible

    const int vsel = g >> 2;   // leftover-tile voxel owned by this lane's c0/c1

    // ---- two 32-column halves ----
    #pragma unroll 1
    for (int h = 0; h < 2; ++h) {
        // B fragments from precomputed table (L1-hot broadcast)
        uint32_t BH[16], BL[16];
        {
            const uint4* bt = (const uint4*)&g_Btab[(h * 32 + lane) * 32];
            #pragma unroll
            for (int i = 0; i < 4; ++i) {
                const uint4 q = bt[i];
                BH[4*i] = q.x; BH[4*i+1] = q.y; BH[4*i+2] = q.z; BH[4*i+3] = q.w;
            }
            #pragma unroll
            for (int i = 0; i < 4; ++i) {
                const uint4 q = bt[4 + i];
                BL[4*i] = q.x; BL[4*i+1] = q.y; BL[4*i+2] = q.z; BL[4*i+3] = q.w;
            }
        }
        #define BHF(nt, ks) (&BH[((nt) * 2 + (ks)) * 2])
        #define BLF(nt, ks) (&BL[((nt) * 2 + (ks)) * 2])

        // leftover tile first (rows 32..47; valid rows 0..7 -> c0/c1)
        float acc2[4][4];
        {
            uint32_t a2h[2][4], a2l[2][4];
            const uint32_t ro2 = (uint32_t)((32 + (lane & 15)) * ASTR + (lane >> 4) * 16);
            ldmat4(a2h[0], aHiB + ro2);      ldmat4(a2h[1], aHiB + ro2 + 32);
            ldmat4(a2l[0], aLoB + ro2);      ldmat4(a2l[1], aLoB + ro2 + 32);
            #pragma unroll
            for (int nt = 0; nt < 4; ++nt)
                acc2[nt][0] = acc2[nt][1] = acc2[nt][2] = acc2[nt][3] = 0.0f;
            #pragma unroll
            for (int ks = 0; ks < 2; ++ks)
                #pragma unroll
                for (int nt = 0; nt < 4; ++nt) {
                    mma16816(acc2[nt], a2h[ks], BHF(nt, ks));
                    mma16816(acc2[nt], a2h[ks], BLF(nt, ks));
                    mma16816(acc2[nt], a2l[ks], BHF(nt, ks));
                }
        }

        // per-voxel tiles + lean shuffle-max epilogue
        #pragma unroll
        for (int vi = 0; vi < VPW; ++vi) {
            uint32_t ah[2][4], al[2][4];
            const uint32_t ro = (uint32_t)((vi * 16 + (lane & 15)) * ASTR + (lane >> 4) * 16);
            ldmat4(ah[0], aHiB + ro);      ldmat4(ah[1], aHiB + ro + 32);
            ldmat4(al[0], aLoB + ro);      ldmat4(al[1], aLoB + ro + 32);
            float acc[4][4];
            #pragma unroll
            for (int nt = 0; nt < 4; ++nt)
                acc[nt][0] = acc[nt][1] = acc[nt][2] = acc[nt][3] = 0.0f;
            #pragma unroll
            for (int ks = 0; ks < 2; ++ks)
                #pragma unroll
                for (int nt = 0; nt < 4; ++nt) {
                    mma16816(acc[nt], ah[ks], BHF(nt, ks));
                    mma16816(acc[nt], ah[ks], BLF(nt, ks));
                    mma16816(acc[nt], al[ks], BHF(nt, ks));
                }

            // per-lane max over rows; merge leftover rows for this voxel
            float pmx[8];
            #pragma unroll
            for (int nt = 0; nt < 4; ++nt) {
                pmx[2*nt]   = fmaxf(acc[nt][0], acc[nt][2]);
                pmx[2*nt+1] = fmaxf(acc[nt][1], acc[nt][3]);
            }
            if (vsel == vi) {
                #pragma unroll
                for (int nt = 0; nt < 4; ++nt) {
                    pmx[2*nt]   = fmaxf(pmx[2*nt],   acc2[nt][0]);
                    pmx[2*nt+1] = fmaxf(pmx[2*nt+1], acc2[nt][1]);
                }
            }

            // lean butterfly over the 8 g-lanes
            const bool b4 = (lane & 16) != 0;
            float q[4];
            #pragma unroll
            for (int i = 0; i < 4; ++i) {
                const float send = b4 ? pmx[i] : pmx[4 + i];
                const float recv = __shfl_xor_sync(0xffffffffu, send, 16);
                q[i] = fmaxf(b4 ? pmx[4 + i] : pmx[i], recv);
            }
            const bool b3 = (lane & 8) != 0;
            float r2v[2];
            #pragma unroll
            for (int i = 0; i < 2; ++i) {
                const float send = b3 ? q[i] : q[2 + i];
                const float recv = __shfl_xor_sync(0xffffffffu, send, 8);
                r2v[i] = fmaxf(b3 ? q[2 + i] : q[i], recv);
            }
            const float f0 = fmaxf(r2v[0], __shfl_xor_sync(0xffffffffu, r2v[0], 4));
            const float f1 = fmaxf(r2v[1], __shfl_xor_sync(0xffffffffu, r2v[1], 4));

            const int vv = v0 + vi;
            if ((lane & 4) == 0 && vv < V) {
                const int ntp = (((lane >> 4) & 1) << 1) | ((lane >> 3) & 1);
                const int col = h * 32 + ntp * 8 + 2 * t4;
                const float2 sh = *(const float2*)&shfs[col];
                float2 r2;
                r2.x = fmaxf(0.0f, f0 + sh.x);
                r2.y = fmaxf(0.0f, f1 + sh.y);
                *(float2*)&out[(size_t)vv * 64 + col] = r2;
            }
        }
        #undef BHF
        #undef BLF
    }
}

extern "C" void kernel_launch(void* const* d_in, const int* in_sizes, int n_in,
                              void* d_out, int out_size) {
    const float4* feats4     = (const float4*)d_in[0];
    const int*    num_points = (const int*)   d_in[1];
    const float*  W          = (const float*) d_in[3];
    const float*  gamma_     = (const float*) d_in[4];
    const float*  beta_      = (const float*) d_in[5];
    const float*  rmean      = (const float*) d_in[6];
    const float*  rvar       = (const float*) d_in[7];
    float* out = (float*)d_out;

    const int V = in_sizes[1];
    lef_prep<<<1, 64>>>(W, gamma_, beta_, rmean, rvar);
    const int vox_per_cta = WARPS * VPW;
    const int grid = (V + vox_per_cta - 1) / vox_per_cta;
    lef_mma4_kernel<<<grid, THREADS>>>(feats4, num_points, out, V);
}

// round 9
// speedup vs baseline: 1.6600x; 1.6600x over previous
#include <cuda_runtime.h>
#include <cuda_fp16.h>
#include <stdint.h>

#define PP 20
#define VPW 4          // voxels per warp
#define WARPS 2
#define THREADS 64
#define ROWS 80        // A rows per warp = 5 m16 tiles
#define ASTR 80        // bytes per A row (32 fp16 = 64B data + 16B pad)

// precomputed by lef_prep: B fragments (BN-scale folded, permuted, fp16 hi/lo)
// layout: [h(2)][lane(32)][ 16 x hi | 16 x lo ]   (idx = (nt*2+ks)*2+pair)
__device__ uint32_t g_Btab[2 * 32 * 32];
__device__ float    g_shift[64];

__device__ __forceinline__ uint32_t smem_u32(const void* p) {
    uint32_t a;
    asm("{ .reg .u64 t; cvta.to.shared.u64 t, %1; cvt.u32.u64 %0, t; }" : "=r"(a) : "l"(p));
    return a;
}
__device__ __forceinline__ float sqrt_apx(float x) {
    float r; asm("sqrt.approx.f32 %0,%1;" : "=f"(r) : "f"(x)); return r;
}
__device__ __forceinline__ uint32_t pack_h2(float x, float y) {
    __half2 t = __floats2half2_rn(x, y);
    return *(uint32_t*)&t;
}
__device__ __forceinline__ uint32_t pack_hres2(float x, float y, uint32_t hipack) {
    __half2 h = *(__half2*)&hipack;
    return pack_h2(x - __half2float(h.x), y - __half2float(h.y));
}
__device__ __forceinline__ void ldmat4(uint32_t* r, uint32_t addr) {
    asm volatile("ldmatrix.sync.aligned.m8n8.x4.shared.b16 {%0,%1,%2,%3}, [%4];"
        : "=r"(r[0]), "=r"(r[1]), "=r"(r[2]), "=r"(r[3]) : "r"(addr));
}
__device__ __forceinline__ void mma16816(float* c, const uint32_t* a, const uint32_t* b) {
    asm volatile("mma.sync.aligned.m16n8k16.row.col.f32.f16.f16.f32 "
        "{%0,%1,%2,%3},{%4,%5,%6,%7},{%8,%9},{%0,%1,%2,%3};"
        : "+f"(c[0]), "+f"(c[1]), "+f"(c[2]), "+f"(c[3])
        : "r"(a[0]), "r"(a[1]), "r"(a[2]), "r"(a[3]), "r"(b[0]), "r"(b[1]));
}
// permuted W lookup: k<20 -> dist weight row 7+k ; 20..26 -> node row k-20 ; else 0
__device__ __forceinline__ float wval(const float* __restrict__ W, int k, int n) {
    if (k < 20) return W[(7 + k) * 64 + n];
    if (k < 27) return W[(k - 20) * 64 + n];
    return 0.0f;
}

// ---- pre-kernel: build B fragment table (fp16 hi/lo, scale-folded) + shift ----
__global__ void lef_prep(const float* __restrict__ W, const float* __restrict__ gamma_,
                         const float* __restrict__ beta_, const float* __restrict__ rmean,
                         const float* __restrict__ rvar)
{
    const int t = threadIdx.x;                    // 64 threads
    {
        const float s = gamma_[t] * rsqrtf(rvar[t] + 1e-3f);
        g_shift[t] = beta_[t] - rmean[t] * s;
    }
    const int h = t >> 5, lane = t & 31, t4 = lane & 3, gg = lane >> 2;
    uint32_t vals[32];
    #pragma unroll
    for (int nt = 0; nt < 4; ++nt) {
        const int nn = h * 32 + nt * 8 + gg;
        const float s = gamma_[nn] * rsqrtf(rvar[nn] + 1e-3f);
        #pragma unroll
        for (int ks = 0; ks < 2; ++ks) {
            const int k0 = ks * 16 + 2 * t4;
            const float w00 = wval(W, k0,     nn) * s;
            const float w01 = wval(W, k0 + 1, nn) * s;
            const float w10 = wval(W, k0 + 8, nn) * s;
            const float w11 = wval(W, k0 + 9, nn) * s;
            const uint32_t h0 = pack_h2(w00, w01);
            const uint32_t h1 = pack_h2(w10, w11);
            vals[(nt * 2 + ks) * 2 + 0] = h0;
            vals[(nt * 2 + ks) * 2 + 1] = h1;
            vals[16 + (nt * 2 + ks) * 2 + 0] = pack_hres2(w00, w01, h0);
            vals[16 + (nt * 2 + ks) * 2 + 1] = pack_hres2(w10, w11, h1);
        }
    }
    uint32_t* dst = &g_Btab[(h * 32 + lane) * 32];
    #pragma unroll
    for (int i = 0; i < 32; ++i) dst[i] = vals[i];
}

__global__ void __launch_bounds__(THREADS, 10) lef_mma5_kernel(
    const float4* __restrict__ feats4,
    const int*    __restrict__ num_points,
    float* __restrict__ out,
    int V)
{
    __shared__ __align__(16) uint8_t Amat[WARPS][ROWS * ASTR];   // fp16, single matrix
    __shared__ float4 cs4s[WARPS * VPW][PP];
    __shared__ float  sqs [WARPS * VPW][PP];
    __shared__ float  meanv[WARPS * VPW][3];
    __shared__ int    npvs[WARPS * VPW];
    __shared__ __align__(8) float shfs[64];

    const int tid  = threadIdx.x;
    const int warp = tid >> 5;
    const int lane = tid & 31;
    const int t4 = lane & 3, g = lane >> 2;

    if (tid < 64) shfs[tid] = g_shift[tid];

    // ---- stage features (coalesced LDG.128) ----
    const int v0 = (blockIdx.x * WARPS + warp) * VPW;
    for (int t = lane; t < VPW * PP; t += 32) {
        const int vi = t / PP, p = t - vi * PP;
        const int vv = v0 + vi;
        float4 f = make_float4(0.f, 0.f, 0.f, 0.f);
        if (vv < V) f = feats4[(size_t)v0 * PP + t];
        const int sv = warp * VPW + vi;
        cs4s[sv][p] = f;
        sqs[sv][p]  = f.x * f.x + f.y * f.y + f.z * f.z;
    }
    if (lane < VPW) {
        const int vv = v0 + lane;
        npvs[warp * VPW + lane] = (vv < V) ? num_points[vv] : 1;
    }
    __syncwarp();

    // ---- per-voxel means (unmasked sum / npts, as reference) ----
    if (lane < 12) {
        const int vi = lane / 3, d = lane - vi * 3;
        const int sv = warp * VPW + vi;
        const float* c = (const float*)&cs4s[sv][0];
        float s = 0.0f;
        #pragma unroll
        for (int p = 0; p < PP; ++p) s += c[p * 4 + d];
        meanv[sv][d] = s / (float)npvs[sv];
    }
    __syncwarp();

    // ---- assemble A rows (single fp16) in voxel-tiled layout ----
    // row r<64: voxel r>>4, point r&15 ; row 64+j: voxel j>>2, point 16+(j&3)
    const uint32_t aB = smem_u32(&Amat[warp][0]);
    #pragma unroll
    for (int r = lane; r < ROWS; r += 32) {
        int vi, p;
        if (r < 64) { vi = r >> 4; p = r & 15; }
        else        { vi = (r - 64) >> 2; p = 16 + ((r - 64) & 3); }
        const int sv = warp * VPW + vi;
        const float4 a  = cs4s[sv][p];
        const float sqp = sqs[sv][p];
        const int   np  = npvs[sv];
        const float pm  = (p < np) ? 1.0f : 0.0f;
        const float m0 = meanv[sv][0], m1 = meanv[sv][1], m2 = meanv[sv][2];

        uint32_t hi[16];
        #pragma unroll
        for (int jj = 0; jj < 10; ++jj) {
            const int q0 = 2 * jj, q1 = q0 + 1;
            const float4 b0 = cs4s[sv][q0], b1 = cs4s[sv][q1];
            float dot0 = a.x * b0.x; dot0 = fmaf(a.y, b0.y, dot0); dot0 = fmaf(a.z, b0.z, dot0);
            float dot1 = a.x * b1.x; dot1 = fmaf(a.y, b1.y, dot1); dot1 = fmaf(a.z, b1.z, dot1);
            const float d20 = (sqp + sqs[sv][q0]) - 2.0f * dot0;
            const float d21 = (sqp + sqs[sv][q1]) - 2.0f * dot1;
            const float e0 = (d20 > 0.0f && q0 < np) ? sqrt_apx(d20) : 0.0f;
            const float e1 = (d21 > 0.0f && q1 < np) ? sqrt_apx(d21) : 0.0f;
            hi[jj] = pack_h2(e0, e1);
        }
        const float n0 = a.x * pm, n1 = a.y * pm, n2 = a.z * pm, n3 = a.w * pm;
        const float n4 = (a.x - m0) * pm, n5 = (a.y - m1) * pm, n6 = (a.z - m2) * pm;
        hi[10] = pack_h2(n0, n1);
        hi[11] = pack_h2(n2, n3);
        hi[12] = pack_h2(n4, n5);
        hi[13] = pack_h2(n6, 0.f);
        hi[14] = hi[15] = 0u;

        uint8_t* rowA = &Amat[warp][r * ASTR];
        const int rot = (lane >> 3) & 3;              // de-conflict STS banks
        #pragma unroll
        for (int jj = 0; jj < 4; ++jj) {
            const int j = (jj + rot) & 3;
            *(uint4*)(rowA + j * 16) = make_uint4(hi[4*j], hi[4*j+1], hi[4*j+2], hi[4*j+3]);
        }
    }
    __syncthreads();   // A tiles + shfs visible

    const int vsel = g >> 2;   // tile-4 voxel owned by acc4[.][0..1]; [2..3] -> vsel+2

    // ---- two 32-column halves ----
    #pragma unroll 1
    for (int h = 0; h < 2; ++h) {
        // B fragments from precomputed table (L1-hot broadcast)
        uint32_t BH[16], BL[16];
        {
            const uint4* bt = (const uint4*)&g_Btab[(h * 32 + lane) * 32];
            #pragma unroll
            for (int i = 0; i < 4; ++i) {
                const uint4 q = bt[i];
                BH[4*i] = q.x; BH[4*i+1] = q.y; BH[4*i+2] = q.z; BH[4*i+3] = q.w;
            }
            #pragma unroll
            for (int i = 0; i < 4; ++i) {
                const uint4 q = bt[4 + i];
                BL[4*i] = q.x; BL[4*i+1] = q.y; BL[4*i+2] = q.z; BL[4*i+3] = q.w;
            }
        }
        #define BHF(nt, ks) (&BH[((nt) * 2 + (ks)) * 2])
        #define BLF(nt, ks) (&BL[((nt) * 2 + (ks)) * 2])

        // tile 4 first (leftover points p=16..19 of all 4 voxels), hold acc4
        float acc4[4][4];
        {
            uint32_t a4[2][4];
            const uint32_t ro4 = (uint32_t)((64 + (lane & 15)) * ASTR + (lane >> 4) * 16);
            ldmat4(a4[0], aB + ro4);      ldmat4(a4[1], aB + ro4 + 32);
            #pragma unroll
            for (int nt = 0; nt < 4; ++nt)
                acc4[nt][0] = acc4[nt][1] = acc4[nt][2] = acc4[nt][3] = 0.0f;
            #pragma unroll
            for (int ks = 0; ks < 2; ++ks)
                #pragma unroll
                for (int nt = 0; nt < 4; ++nt) {
                    mma16816(acc4[nt], a4[ks], BHF(nt, ks));
                    mma16816(acc4[nt], a4[ks], BLF(nt, ks));
                }
        }

        // per-voxel tiles + lean shuffle-max epilogue
        #pragma unroll
        for (int vi = 0; vi < VPW; ++vi) {
            uint32_t af[2][4];
            const uint32_t ro = (uint32_t)((vi * 16 + (lane & 15)) * ASTR + (lane >> 4) * 16);
            ldmat4(af[0], aB + ro);      ldmat4(af[1], aB + ro + 32);
            float acc[4][4];
            #pragma unroll
            for (int nt = 0; nt < 4; ++nt)
                acc[nt][0] = acc[nt][1] = acc[nt][2] = acc[nt][3] = 0.0f;
            #pragma unroll
            for (int ks = 0; ks < 2; ++ks)
                #pragma unroll
                for (int nt = 0; nt < 4; ++nt) {
                    mma16816(acc[nt], af[ks], BHF(nt, ks));
                    mma16816(acc[nt], af[ks], BLF(nt, ks));
                }

            // per-lane max over this voxel's rows (p 0..15), merge tile-4 rows
            float pmx[8];
            #pragma unroll
            for (int nt = 0; nt < 4; ++nt) {
                pmx[2*nt]   = fmaxf(acc[nt][0], acc[nt][2]);
                pmx[2*nt+1] = fmaxf(acc[nt][1], acc[nt][3]);
            }
            if (vsel == vi) {
                #pragma unroll
                for (int nt = 0; nt < 4; ++nt) {
                    pmx[2*nt]   = fmaxf(pmx[2*nt],   acc4[nt][0]);
                    pmx[2*nt+1] = fmaxf(pmx[2*nt+1], acc4[nt][1]);
                }
            }
            if (vsel == vi - 2) {
                #pragma unroll
                for (int nt = 0; nt < 4; ++nt) {
                    pmx[2*nt]   = fmaxf(pmx[2*nt],   acc4[nt][2]);
                    pmx[2*nt+1] = fmaxf(pmx[2*nt+1], acc4[nt][3]);
                }
            }

            // lean butterfly: drop half the values each round
            const bool b4 = (lane & 16) != 0;
            float q[4];
            #pragma unroll
            for (int i = 0; i < 4; ++i) {
                const float send = b4 ? pmx[i] : pmx[4 + i];
                const float recv = __shfl_xor_sync(0xffffffffu, send, 16);
                q[i] = fmaxf(b4 ? pmx[4 + i] : pmx[i], recv);
            }
            const bool b3 = (lane & 8) != 0;
            float r2v[2];
            #pragma unroll
            for (int i = 0; i < 2; ++i) {
                const float send = b3 ? q[i] : q[2 + i];
                const float recv = __shfl_xor_sync(0xffffffffu, send, 8);
                r2v[i] = fmaxf(b3 ? q[2 + i] : q[i], recv);
            }
            const float f0 = fmaxf(r2v[0], __shfl_xor_sync(0xffffffffu, r2v[0], 4));
            const float f1 = fmaxf(r2v[1], __shfl_xor_sync(0xffffffffu, r2v[1], 4));

            // lanes with bit2==0 store cols ntp*8 + 2*t4 (+1)
            const int vv = v0 + vi;
            if ((lane & 4) == 0 && vv < V) {
                const int ntp = (((lane >> 4) & 1) << 1) | ((lane >> 3) & 1);
                const int col = h * 32 + ntp * 8 + 2 * t4;
                const float2 sh = *(const float2*)&shfs[col];
                float2 r2;
                r2.x = fmaxf(0.0f, f0 + sh.x);
                r2.y = fmaxf(0.0f, f1 + sh.y);
                *(float2*)&out[(size_t)vv * 64 + col] = r2;
            }
        }
        #undef BHF
        #undef BLF
    }
}

extern "C" void kernel_launch(void* const* d_in, const int* in_sizes, int n_in,
                              void* d_out, int out_size) {
    const float4* feats4     = (const float4*)d_in[0];
    const int*    num_points = (const int*)   d_in[1];
    const float*  W          = (const float*) d_in[3];
    const float*  gamma_     = (const float*) d_in[4];
    const float*  beta_      = (const float*) d_in[5];
    const float*  rmean      = (const float*) d_in[6];
    const float*  rvar       = (const float*) d_in[7];
    float* out = (float*)d_out;

    const int V = in_sizes[1];
    lef_prep<<<1, 64>>>(W, gamma_, beta_, rmean, rvar);
    const int vox_per_cta = WARPS * VPW;
    const int grid = (V + vox_per_cta - 1) / vox_per_cta;
    lef_mma5_kernel<<<grid, THREADS>>>(feats4, num_points, out, V);
}

// round 10
// speedup vs baseline: 1.6821x; 1.0133x over previous
#include <cuda_runtime.h>
#include <cuda_fp16.h>
#include <stdint.h>

#define PP 20
#define VPW 4          // voxels per warp
#define WARPS 2
#define THREADS 64
#define ROWS 80        // A rows per warp = 5 m16 tiles
#define ASTR 80        // bytes per A row (32 fp16 = 64B data + 16B pad)

// precomputed by lef_prep: B fragments (BN-scale folded, permuted, fp16 hi/lo)
// layout: [h(2)][lane(32)][ 16 x hi | 16 x lo ]   (idx = (nt*2+ks)*2+pair)
__device__ uint32_t g_Btab[2 * 32 * 32];
__device__ float    g_shift[64];

__device__ __forceinline__ uint32_t smem_u32(const void* p) {
    uint32_t a;
    asm("{ .reg .u64 t; cvta.to.shared.u64 t, %1; cvt.u32.u64 %0, t; }" : "=r"(a) : "l"(p));
    return a;
}
__device__ __forceinline__ float sqrt_apx(float x) {
    float r; asm("sqrt.approx.f32 %0,%1;" : "=f"(r) : "f"(x)); return r;
}
__device__ __forceinline__ uint32_t pack_h2(float x, float y) {
    __half2 t = __floats2half2_rn(x, y);
    return *(uint32_t*)&t;
}
__device__ __forceinline__ uint32_t pack_hres2(float x, float y, uint32_t hipack) {
    __half2 h = *(__half2*)&hipack;
    return pack_h2(x - __half2float(h.x), y - __half2float(h.y));
}
__device__ __forceinline__ void ldmat4(uint32_t* r, uint32_t addr) {
    asm volatile("ldmatrix.sync.aligned.m8n8.x4.shared.b16 {%0,%1,%2,%3}, [%4];"
        : "=r"(r[0]), "=r"(r[1]), "=r"(r[2]), "=r"(r[3]) : "r"(addr));
}
__device__ __forceinline__ void mma16816(float* c, const uint32_t* a, const uint32_t* b) {
    asm volatile("mma.sync.aligned.m16n8k16.row.col.f32.f16.f16.f32 "
        "{%0,%1,%2,%3},{%4,%5,%6,%7},{%8,%9},{%0,%1,%2,%3};"
        : "+f"(c[0]), "+f"(c[1]), "+f"(c[2]), "+f"(c[3])
        : "r"(a[0]), "r"(a[1]), "r"(a[2]), "r"(a[3]), "r"(b[0]), "r"(b[1]));
}
// permuted W lookup: k<20 -> dist weight row 7+k ; 20..26 -> node row k-20 ; else 0
__device__ __forceinline__ float wval(const float* __restrict__ W, int k, int n) {
    if (k < 20) return W[(7 + k) * 64 + n];
    if (k < 27) return W[(k - 20) * 64 + n];
    return 0.0f;
}

// ---- pre-kernel: build B fragment table (fp16 hi/lo, scale-folded) + shift ----
__global__ void lef_prep(const float* __restrict__ W, const float* __restrict__ gamma_,
                         const float* __restrict__ beta_, const float* __restrict__ rmean,
                         const float* __restrict__ rvar)
{
    const int t = threadIdx.x;                    // 64 threads
    {
        const float s = gamma_[t] * rsqrtf(rvar[t] + 1e-3f);
        g_shift[t] = beta_[t] - rmean[t] * s;
    }
    const int h = t >> 5, lane = t & 31, t4 = lane & 3, gg = lane >> 2;
    uint32_t vals[32];
    #pragma unroll
    for (int nt = 0; nt < 4; ++nt) {
        const int nn = h * 32 + nt * 8 + gg;
        const float s = gamma_[nn] * rsqrtf(rvar[nn] + 1e-3f);
        #pragma unroll
        for (int ks = 0; ks < 2; ++ks) {
            const int k0 = ks * 16 + 2 * t4;
            const float w00 = wval(W, k0,     nn) * s;
            const float w01 = wval(W, k0 + 1, nn) * s;
            const float w10 = wval(W, k0 + 8, nn) * s;
            const float w11 = wval(W, k0 + 9, nn) * s;
            const uint32_t h0 = pack_h2(w00, w01);
            const uint32_t h1 = pack_h2(w10, w11);
            vals[(nt * 2 + ks) * 2 + 0] = h0;
            vals[(nt * 2 + ks) * 2 + 1] = h1;
            vals[16 + (nt * 2 + ks) * 2 + 0] = pack_hres2(w00, w01, h0);
            vals[16 + (nt * 2 + ks) * 2 + 1] = pack_hres2(w10, w11, h1);
        }
    }
    uint32_t* dst = &g_Btab[(h * 32 + lane) * 32];
    #pragma unroll
    for (int i = 0; i < 32; ++i) dst[i] = vals[i];
}

__global__ void __launch_bounds__(THREADS, 10) lef_mma6_kernel(
    const float4* __restrict__ feats4,
    const int*    __restrict__ num_points,
    float* __restrict__ out,
    int V)
{
    __shared__ __align__(16) uint8_t Amat[WARPS][ROWS * ASTR];   // fp16, single matrix
    __shared__ float4 cs4s[WARPS * VPW][PP];
    __shared__ float  meanv[WARPS * VPW][3];
    __shared__ int    npvs[WARPS * VPW];
    __shared__ __align__(8) float shfs[64];

    const int tid  = threadIdx.x;
    const int warp = tid >> 5;
    const int lane = tid & 31;
    const int t4 = lane & 3, g = lane >> 2;

    if (tid < 64) shfs[tid] = g_shift[tid];

    // ---- stage features (coalesced LDG.128) ----
    const int v0 = (blockIdx.x * WARPS + warp) * VPW;
    for (int t = lane; t < VPW * PP; t += 32) {
        const int vi = t / PP, p = t - vi * PP;
        const int vv = v0 + vi;
        float4 f = make_float4(0.f, 0.f, 0.f, 0.f);
        if (vv < V) f = feats4[(size_t)v0 * PP + t];
        cs4s[warp * VPW + vi][p] = f;
    }
    if (lane < VPW) {
        const int vv = v0 + lane;
        npvs[warp * VPW + lane] = (vv < V) ? num_points[vv] : 1;
    }
    __syncwarp();

    // ---- per-voxel means (unmasked sum / npts, as reference) ----
    if (lane < 12) {
        const int vi = lane / 3, d = lane - vi * 3;
        const int sv = warp * VPW + vi;
        const float* c = (const float*)&cs4s[sv][0];
        float s = 0.0f;
        #pragma unroll
        for (int p = 0; p < PP; ++p) s += c[p * 4 + d];
        meanv[sv][d] = s / (float)npvs[sv];
    }
    __syncwarp();

    // ---- assemble A rows (single fp16), direct-difference distances ----
    // row r<64: voxel r>>4, point r&15 ; row 64+j: voxel j>>2, point 16+(j&3)
    const uint32_t aB = smem_u32(&Amat[warp][0]);
    #pragma unroll
    for (int r = lane; r < ROWS; r += 32) {
        int vi, p;
        if (r < 64) { vi = r >> 4; p = r & 15; }
        else        { vi = (r - 64) >> 2; p = 16 + ((r - 64) & 3); }
        const int sv = warp * VPW + vi;
        const float4 a  = cs4s[sv][p];
        const int   np  = npvs[sv];
        const float pm  = (p < np) ? 1.0f : 0.0f;
        const float m0 = meanv[sv][0], m1 = meanv[sv][1], m2 = meanv[sv][2];

        uint32_t hi[16];
        #pragma unroll
        for (int jj = 0; jj < 10; ++jj) {
            const int q0 = 2 * jj, q1 = q0 + 1;
            const float4 b0 = cs4s[sv][q0], b1 = cs4s[sv][q1];
            const float dx0 = a.x - b0.x, dy0 = a.y - b0.y, dz0 = a.z - b0.z;
            const float dx1 = a.x - b1.x, dy1 = a.y - b1.y, dz1 = a.z - b1.z;
            float d20 = dx0 * dx0; d20 = fmaf(dy0, dy0, d20); d20 = fmaf(dz0, dz0, d20);
            float d21 = dx1 * dx1; d21 = fmaf(dy1, dy1, d21); d21 = fmaf(dz1, dz1, d21);
            const float e0 = (d20 > 0.0f && q0 < np) ? sqrt_apx(d20) : 0.0f;
            const float e1 = (d21 > 0.0f && q1 < np) ? sqrt_apx(d21) : 0.0f;
            hi[jj] = pack_h2(e0, e1);
        }
        const float n0 = a.x * pm, n1 = a.y * pm, n2 = a.z * pm, n3 = a.w * pm;
        const float n4 = (a.x - m0) * pm, n5 = (a.y - m1) * pm, n6 = (a.z - m2) * pm;
        hi[10] = pack_h2(n0, n1);
        hi[11] = pack_h2(n2, n3);
        hi[12] = pack_h2(n4, n5);
        hi[13] = pack_h2(n6, 0.f);
        hi[14] = hi[15] = 0u;

        uint8_t* rowA = &Amat[warp][r * ASTR];
        const int rot = (lane >> 3) & 3;              // de-conflict STS banks
        #pragma unroll
        for (int jj = 0; jj < 4; ++jj) {
            const int j = (jj + rot) & 3;
            *(uint4*)(rowA + j * 16) = make_uint4(hi[4*j], hi[4*j+1], hi[4*j+2], hi[4*j+3]);
        }
    }
    __syncthreads();   // A tiles + shfs visible

    const int vsel = g >> 2;   // tile-4 voxel owned by acc4[.][0..1]; [2..3] -> vsel+2

    // ---- two 32-column halves ----
    #pragma unroll 1
    for (int h = 0; h < 2; ++h) {
        // B fragments from precomputed table (L1-hot broadcast)
        uint32_t BH[16], BL[16];
        {
            const uint4* bt = (const uint4*)&g_Btab[(h * 32 + lane) * 32];
            #pragma unroll
            for (int i = 0; i < 4; ++i) {
                const uint4 q = bt[i];
                BH[4*i] = q.x; BH[4*i+1] = q.y; BH[4*i+2] = q.z; BH[4*i+3] = q.w;
            }
            #pragma unroll
            for (int i = 0; i < 4; ++i) {
                const uint4 q = bt[4 + i];
                BL[4*i] = q.x; BL[4*i+1] = q.y; BL[4*i+2] = q.z; BL[4*i+3] = q.w;
            }
        }
        #define BHF(nt, ks) (&BH[((nt) * 2 + (ks)) * 2])
        #define BLF(nt, ks) (&BL[((nt) * 2 + (ks)) * 2])

        // tile 4 first (leftover points p=16..19 of all 4 voxels), hold acc4
        float acc4[4][4];
        {
            uint32_t a4[2][4];
            const uint32_t ro4 = (uint32_t)((64 + (lane & 15)) * ASTR + (lane >> 4) * 16);
            ldmat4(a4[0], aB + ro4);      ldmat4(a4[1], aB + ro4 + 32);
            #pragma unroll
            for (int nt = 0; nt < 4; ++nt)
                acc4[nt][0] = acc4[nt][1] = acc4[nt][2] = acc4[nt][3] = 0.0f;
            #pragma unroll
            for (int ks = 0; ks < 2; ++ks)
                #pragma unroll
                for (int nt = 0; nt < 4; ++nt) {
                    mma16816(acc4[nt], a4[ks], BHF(nt, ks));
                    mma16816(acc4[nt], a4[ks], BLF(nt, ks));
                }
        }

        // per-voxel tiles + lean shuffle-max epilogue
        #pragma unroll
        for (int vi = 0; vi < VPW; ++vi) {
            uint32_t af[2][4];
            const uint32_t ro = (uint32_t)((vi * 16 + (lane & 15)) * ASTR + (lane >> 4) * 16);
            ldmat4(af[0], aB + ro);      ldmat4(af[1], aB + ro + 32);
            float acc[4][4];
            #pragma unroll
            for (int nt = 0; nt < 4; ++nt)
                acc[nt][0] = acc[nt][1] = acc[nt][2] = acc[nt][3] = 0.0f;
            #pragma unroll
            for (int ks = 0; ks < 2; ++ks)
                #pragma unroll
                for (int nt = 0; nt < 4; ++nt) {
                    mma16816(acc[nt], af[ks], BHF(nt, ks));
                    mma16816(acc[nt], af[ks], BLF(nt, ks));
                }

            // per-lane max over this voxel's rows (p 0..15), merge tile-4 rows
            float pmx[8];
            #pragma unroll
            for (int nt = 0; nt < 4; ++nt) {
                pmx[2*nt]   = fmaxf(acc[nt][0], acc[nt][2]);
                pmx[2*nt+1] = fmaxf(acc[nt][1], acc[nt][3]);
            }
            if (vsel == vi) {
                #pragma unroll
                for (int nt = 0; nt < 4; ++nt) {
                    pmx[2*nt]   = fmaxf(pmx[2*nt],   acc4[nt][0]);
                    pmx[2*nt+1] = fmaxf(pmx[2*nt+1], acc4[nt][1]);
                }
            }
            if (vsel == vi - 2) {
                #pragma unroll
                for (int nt = 0; nt < 4; ++nt) {
                    pmx[2*nt]   = fmaxf(pmx[2*nt],   acc4[nt][2]);
                    pmx[2*nt+1] = fmaxf(pmx[2*nt+1], acc4[nt][3]);
                }
            }

            // lean butterfly: drop half the values each round
            const bool b4 = (lane & 16) != 0;
            float q[4];
            #pragma unroll
            for (int i = 0; i < 4; ++i) {
                const float send = b4 ? pmx[i] : pmx[4 + i];
                const float recv = __shfl_xor_sync(0xffffffffu, send, 16);
                q[i] = fmaxf(b4 ? pmx[4 + i] : pmx[i], recv);
            }
            const bool b3 = (lane & 8) != 0;
            float r2v[2];
            #pragma unroll
            for (int i = 0; i < 2; ++i) {
                const float send = b3 ? q[i] : q[2 + i];
                const float recv = __shfl_xor_sync(0xffffffffu, send, 8);
                r2v[i] = fmaxf(b3 ? q[2 + i] : q[i], recv);
            }
            const float f0 = fmaxf(r2v[0], __shfl_xor_sync(0xffffffffu, r2v[0], 4));
            const float f1 = fmaxf(r2v[1], __shfl_xor_sync(0xffffffffu, r2v[1], 4));

            // lanes with bit2==0 store cols ntp*8 + 2*t4 (+1)
            const int vv = v0 + vi;
            if ((lane & 4) == 0 && vv < V) {
                const int ntp = (((lane >> 4) & 1) << 1) | ((lane >> 3) & 1);
                const int col = h * 32 + ntp * 8 + 2 * t4;
                const float2 sh = *(const float2*)&shfs[col];
                float2 r2;
                r2.x = fmaxf(0.0f, f0 + sh.x);
                r2.y = fmaxf(0.0f, f1 + sh.y);
                *(float2*)&out[(size_t)vv * 64 + col] = r2;
            }
        }
        #undef BHF
        #undef BLF
    }
}

extern "C" void kernel_launch(void* const* d_in, const int* in_sizes, int n_in,
                              void* d_out, int out_size) {
    const float4* feats4     = (const float4*)d_in[0];
    const int*    num_points = (const int*)   d_in[1];
    const float*  W          = (const float*) d_in[3];
    const float*  gamma_     = (const float*) d_in[4];
    const float*  beta_      = (const float*) d_in[5];
    const float*  rmean      = (const float*) d_in[6];
    const float*  rvar       = (const float*) d_in[7];
    float* out = (float*)d_out;

    const int V = in_sizes[1];
    lef_prep<<<1, 64>>>(W, gamma_, beta_, rmean, rvar);
    const int vox_per_cta = WARPS * VPW;
    const int grid = (V + vox_per_cta - 1) / vox_per_cta;
    lef_mma6_kernel<<<grid, THREADS>>>(feats4, num_points, out, V);
}